// round 9
// baseline (speedup 1.0000x reference)
#include <cuda_runtime.h>
#include <cuda_bf16.h>

#define H 40
#define T 256
#define BATCH 8192
#define EPB 32            // elements per block (2 pairs x 16)
#define THREADS 128       // 4 warps: pair p = warps {2p, 2p+1}; even warp = role A
#define NB 4
#define NBLOCKS (BATCH / EPB)   // 256

typedef unsigned long long u64;

// ---- shared memory layout (float offsets), identical to R6 ----
#define OFF_WIH1 0                       // [k 40][c 3][g 4]      = 480
#define OFF_B1   480                     // [k 40][g 4]           = 160
#define OFF_B2   640                     // [k 40][g 4]           = 160
#define OFF_WHH1 800                     // [k 40][kk pitch41][g4]= 6560
#define OFF_WIH2 (800 + 6560)            // 7360
#define OFF_WHH2 (800 + 2*6560)          // 13920
#define OFF_HC   (800 + 3*6560)          // 20480 : [e 32][kk 41] float4 {h1,h1,h2,h2}
#define HC_ESTRIDE 164                   // 41 float4 = 164 floats
#define SMEM_FLOATS (OFF_HC + EPB * HC_ESTRIDE)   // 25728
#define SMEM_BYTES (SMEM_FLOATS * 4)     // 102912 -> 2 CTAs/SM

__device__ __forceinline__ void fma2(u64 &d, u64 a, u64 b) {
    asm("fma.rn.f32x2 %0, %1, %2, %0;" : "+l"(d) : "l"(a), "l"(b));
}
__device__ __forceinline__ u64 pack2(float x, float y) {
    u64 r; asm("mov.b64 %0, {%1, %2};" : "=l"(r) : "f"(x), "f"(y)); return r;
}
__device__ __forceinline__ void unpack2(u64 v, float &x, float &y) {
    asm("mov.b64 {%0, %1}, %2;" : "=f"(x), "=f"(y) : "l"(v));
}
__device__ __forceinline__ float tanhfast(float x) {
    float y; asm("tanh.approx.f32 %0, %1;" : "=f"(y) : "f"(x)); return y;
}
__device__ __forceinline__ float sigf(float x) {
    return fmaf(0.5f, tanhfast(0.5f * x), 0.5f);
}
__device__ __forceinline__ void barsync() {
    asm volatile("bar.sync 0;" ::: "memory");
}

__global__ __launch_bounds__(THREADS)
void lstm2_ws_kernel(const float* __restrict__ x,
                     const float* __restrict__ W_ih1,
                     const float* __restrict__ W_hh1,
                     const float* __restrict__ b1,
                     const float* __restrict__ W_ih2,
                     const float* __restrict__ W_hh2,
                     const float* __restrict__ b2,
                     const float* __restrict__ W_fc,
                     const float* __restrict__ b_fc,
                     float* __restrict__ out)
{
    extern __shared__ float sm[];
    const int tid = threadIdx.x;

    // ---- stage weights, gate-interleaved (all 128 threads) ----
    for (int idx = tid; idx < 160 * 3; idx += THREADS) {
        int row = idx / 3, c = idx % 3;
        int g = row / H, k = row % H;
        sm[OFF_WIH1 + (k * 3 + c) * 4 + g] = W_ih1[idx];
    }
    for (int idx = tid; idx < 160; idx += THREADS) {
        int g = idx / H, k = idx % H;
        sm[OFF_B1 + k * 4 + g] = b1[idx];
        sm[OFF_B2 + k * 4 + g] = b2[idx];
    }
    for (int idx = tid; idx < 160 * H; idx += THREADS) {
        int row = idx / H, kk = idx % H;
        int g = row / H, k = row % H;
        sm[OFF_WHH1 + (k * 41 + kk) * 4 + g] = W_hh1[idx];
        sm[OFF_WIH2 + (k * 41 + kk) * 4 + g] = W_ih2[idx];
        sm[OFF_WHH2 + (k * 41 + kk) * 4 + g] = W_hh2[idx];
    }
    for (int idx = tid; idx < EPB * HC_ESTRIDE; idx += THREADS) {
        sm[OFF_HC + idx] = 0.0f;
    }
    __syncthreads();

    const int lane  = tid & 31;
    const int warp  = tid >> 5;
    const int pair  = warp >> 1;
    const bool roleA = ((warp & 1) == 0);
    const int j    = lane & 7;     // k-slice (owns units k0..k0+4 in its domain)
    const int sub  = lane >> 3;    // 0..3
    const int k0   = j * 5;

    int eb[NB];
    long ge[NB];
    const float* xb[NB];
    #pragma unroll
    for (int b = 0; b < NB; b++) {
        eb[b] = pair * 16 + b * 4 + sub;
        ge[b] = (long)blockIdx.x * EPB + eb[b];
        xb[b] = x + ge[b] * (T * 3);
    }

    float* __restrict__ HC = sm + OFF_HC;

    if (roleA) {
        // ============ ROLE A: layer-1 (all 40 units) + layer-2 unit k0 ============
        float c1[5][NB], c2a[NB];
        u64 a1A[5][NB], a1B[5][NB];   // L1 gate accs (i,f)/(g,o)
        u64 a2A[NB], a2B[NB];         // L2 accs for unit k0
        float xv[NB][3], xn[NB][3];
        #pragma unroll
        for (int k = 0; k < 5; k++)
            #pragma unroll
            for (int b = 0; b < NB; b++) c1[k][b] = 0.0f;
        #pragma unroll
        for (int b = 0; b < NB; b++) c2a[b] = 0.0f;
        #pragma unroll
        for (int b = 0; b < NB; b++)
            #pragma unroll
            for (int c = 0; c < 3; c++)
                xv[b][c] = __ldg(xb[b] + c);

        for (int n = 0; n <= T; n++) {
            const bool doL1 = (n < T);
            const bool doL2 = (n >= 1);

            // ---------- phase M: matvecs (read old HC) ----------
            if (doL1) {
                int tn = (n + 1 < T) ? (n + 1) : (T - 1);
                #pragma unroll
                for (int b = 0; b < NB; b++)
                    #pragma unroll
                    for (int c = 0; c < 3; c++)
                        xn[b][c] = __ldg(xb[b] + tn * 3 + c);

                #pragma unroll
                for (int k = 0; k < 5; k++) {
                    ulonglong2 bb = *(const ulonglong2*)(sm + OFF_B1 + (k0 + k) * 4);
                    #pragma unroll
                    for (int b = 0; b < NB; b++) { a1A[k][b] = bb.x; a1B[k][b] = bb.y; }
                }
                #pragma unroll
                for (int c = 0; c < 3; c++) {
                    u64 xp[NB];
                    #pragma unroll
                    for (int b = 0; b < NB; b++) xp[b] = pack2(xv[b][c], xv[b][c]);
                    #pragma unroll
                    for (int k = 0; k < 5; k++) {
                        ulonglong2 w = *(const ulonglong2*)(sm + OFF_WIH1 + ((k0 + k) * 3 + c) * 4);
                        #pragma unroll
                        for (int b = 0; b < NB; b++) {
                            fma2(a1A[k][b], w.x, xp[b]);
                            fma2(a1B[k][b], w.y, xp[b]);
                        }
                    }
                }
                #pragma unroll 5
                for (int kk = 0; kk < H; kk++) {
                    u64 hp[NB];   // {h1,h1} = .xy of HC
                    #pragma unroll
                    for (int b = 0; b < NB; b++)
                        hp[b] = *(const u64*)(HC + eb[b] * HC_ESTRIDE + kk * 4);
                    #pragma unroll
                    for (int k = 0; k < 5; k++) {
                        ulonglong2 w = *(const ulonglong2*)(sm + OFF_WHH1 + ((k0 + k) * 41 + kk) * 4);
                        #pragma unroll
                        for (int b = 0; b < NB; b++) {
                            fma2(a1A[k][b], w.x, hp[b]);
                            fma2(a1B[k][b], w.y, hp[b]);
                        }
                    }
                }
            }
            if (doL2) {
                ulonglong2 bb = *(const ulonglong2*)(sm + OFF_B2 + k0 * 4);
                #pragma unroll
                for (int b = 0; b < NB; b++) { a2A[b] = bb.x; a2B[b] = bb.y; }
                #pragma unroll 5
                for (int kk = 0; kk < H; kk++) {
                    ulonglong2 hq[NB];   // .x={h1,h1}, .y={h2,h2}
                    #pragma unroll
                    for (int b = 0; b < NB; b++)
                        hq[b] = *(const ulonglong2*)(HC + eb[b] * HC_ESTRIDE + kk * 4);
                    ulonglong2 w1 = *(const ulonglong2*)(sm + OFF_WIH2 + (k0 * 41 + kk) * 4);
                    ulonglong2 w2 = *(const ulonglong2*)(sm + OFF_WHH2 + (k0 * 41 + kk) * 4);
                    #pragma unroll
                    for (int b = 0; b < NB; b++) {
                        fma2(a2A[b], w1.x, hq[b].x);
                        fma2(a2B[b], w1.y, hq[b].x);
                        fma2(a2A[b], w2.x, hq[b].y);
                        fma2(a2B[b], w2.y, hq[b].y);
                    }
                }
            }
            barsync();

            // ---------- phase W: activations + HC writes ----------
            if (doL1) {
                #pragma unroll
                for (int k = 0; k < 5; k++) {
                    #pragma unroll
                    for (int b = 0; b < NB; b++) {
                        float gi, gf, gg, go;
                        unpack2(a1A[k][b], gi, gf);
                        unpack2(a1B[k][b], gg, go);
                        gi = sigf(gi); gf = sigf(gf); gg = tanhfast(gg); go = sigf(go);
                        c1[k][b] = fmaf(gf, c1[k][b], gi * gg);
                        float h = go * tanhfast(c1[k][b]);
                        *(u64*)(HC + eb[b] * HC_ESTRIDE + (k0 + k) * 4) = pack2(h, h);
                    }
                }
                #pragma unroll
                for (int b = 0; b < NB; b++) {
                    xv[b][0] = xn[b][0]; xv[b][1] = xn[b][1]; xv[b][2] = xn[b][2];
                }
            }
            if (doL2) {
                #pragma unroll
                for (int b = 0; b < NB; b++) {
                    float gi, gf, gg, go;
                    unpack2(a2A[b], gi, gf);
                    unpack2(a2B[b], gg, go);
                    gi = sigf(gi); gf = sigf(gf); gg = tanhfast(gg); go = sigf(go);
                    c2a[b] = fmaf(gf, c2a[b], gi * gg);
                    float h = go * tanhfast(c2a[b]);
                    *(u64*)(HC + eb[b] * HC_ESTRIDE + k0 * 4 + 2) = pack2(h, h);
                }
            }
            barsync();
        }
    } else {
        // ============ ROLE B: layer-2 units k0+1 .. k0+4 ============
        float c2[4][NB];
        u64 a2A[4][NB], a2B[4][NB];
        #pragma unroll
        for (int m = 0; m < 4; m++)
            #pragma unroll
            for (int b = 0; b < NB; b++) c2[m][b] = 0.0f;

        for (int n = 0; n <= T; n++) {
            const bool doL2 = (n >= 1);

            // ---------- phase M ----------
            if (doL2) {
                #pragma unroll
                for (int m = 0; m < 4; m++) {
                    ulonglong2 bb = *(const ulonglong2*)(sm + OFF_B2 + (k0 + 1 + m) * 4);
                    #pragma unroll
                    for (int b = 0; b < NB; b++) { a2A[m][b] = bb.x; a2B[m][b] = bb.y; }
                }
                #pragma unroll 5
                for (int kk = 0; kk < H; kk++) {
                    ulonglong2 hq[NB];
                    #pragma unroll
                    for (int b = 0; b < NB; b++)
                        hq[b] = *(const ulonglong2*)(HC + eb[b] * HC_ESTRIDE + kk * 4);
                    #pragma unroll
                    for (int m = 0; m < 4; m++) {
                        ulonglong2 w1 = *(const ulonglong2*)(sm + OFF_WIH2 + ((k0 + 1 + m) * 41 + kk) * 4);
                        ulonglong2 w2 = *(const ulonglong2*)(sm + OFF_WHH2 + ((k0 + 1 + m) * 41 + kk) * 4);
                        #pragma unroll
                        for (int b = 0; b < NB; b++) {
                            fma2(a2A[m][b], w1.x, hq[b].x);
                            fma2(a2B[m][b], w1.y, hq[b].x);
                            fma2(a2A[m][b], w2.x, hq[b].y);
                            fma2(a2B[m][b], w2.y, hq[b].y);
                        }
                    }
                }
            }
            barsync();

            // ---------- phase W ----------
            if (doL2) {
                #pragma unroll
                for (int m = 0; m < 4; m++) {
                    #pragma unroll
                    for (int b = 0; b < NB; b++) {
                        float gi, gf, gg, go;
                        unpack2(a2A[m][b], gi, gf);
                        unpack2(a2B[m][b], gg, go);
                        gi = sigf(gi); gf = sigf(gf); gg = tanhfast(gg); go = sigf(go);
                        c2[m][b] = fmaf(gf, c2[m][b], gi * gg);
                        float h = go * tanhfast(c2[m][b]);
                        *(u64*)(HC + eb[b] * HC_ESTRIDE + (k0 + 1 + m) * 4 + 2) = pack2(h, h);
                    }
                }
            }
            barsync();
        }
    }
    __syncthreads();

    // ================= FC epilogue (role-A warps, j<2) =================
    if (roleA && j < 2) {
        float wfc[H];
        #pragma unroll 8
        for (int kk = 0; kk < H; kk++) wfc[kk] = W_fc[j * H + kk];
        float bias = b_fc[j];
        #pragma unroll
        for (int b = 0; b < NB; b++) {
            float acc = bias;
            #pragma unroll 8
            for (int kk = 0; kk < H; kk++) {
                float hlo, hhi;
                unpack2(*(const u64*)(HC + eb[b] * HC_ESTRIDE + kk * 4 + 2), hlo, hhi);
                acc = fmaf(hlo, wfc[kk], acc);
            }
            out[ge[b] * 2 + j] = acc;
        }
    }
}

extern "C" void kernel_launch(void* const* d_in, const int* in_sizes, int n_in,
                              void* d_out, int out_size)
{
    const float* x     = (const float*)d_in[0];
    const float* W_ih1 = (const float*)d_in[1];
    const float* W_hh1 = (const float*)d_in[2];
    const float* b1    = (const float*)d_in[3];
    const float* W_ih2 = (const float*)d_in[4];
    const float* W_hh2 = (const float*)d_in[5];
    const float* b2    = (const float*)d_in[6];
    const float* W_fc  = (const float*)d_in[7];
    const float* b_fc  = (const float*)d_in[8];
    float* out = (float*)d_out;

    cudaFuncSetAttribute(lstm2_ws_kernel,
                         cudaFuncAttributeMaxDynamicSharedMemorySize, SMEM_BYTES);

    lstm2_ws_kernel<<<NBLOCKS, THREADS, SMEM_BYTES>>>(
        x, W_ih1, W_hh1, b1, W_ih2, W_hh2, b2, W_fc, b_fc, out);
}

// round 10
// speedup vs baseline: 2.7201x; 2.7201x over previous
#include <cuda_runtime.h>
#include <cuda_bf16.h>
#include <cstdint>

#define H 40
#define T 256
#define BATCH 8192
#define EPB 32
#define THREADS 256
#define NBLOCKS (BATCH / EPB)   // 256

#define PITCH 104               // bf16 cols per element row in HS arrays
#define NFRAG 180               // L1: 3 kt x 20 nt ; L2: 6 kt x 20 nt
#define OFF_BF 0
#define OFF_HSHI (NFRAG * 32 * 16)             // 92160 B
#define OFF_HSLO (OFF_HSHI + 32 * PITCH * 2)   // +6656
#define SMEM_BYTES (OFF_HSLO + 32 * PITCH * 2) // 105472 B -> 2 CTAs/SM

__device__ __forceinline__ float tanhfast(float x) {
    float y; asm("tanh.approx.f32 %0, %1;" : "=f"(y) : "f"(x)); return y;
}
__device__ __forceinline__ float sigf(float x) {
    return fmaf(0.5f, tanhfast(0.5f * x), 0.5f);
}
__device__ __forceinline__ void bsplit(float v, __nv_bfloat16 &hi, __nv_bfloat16 &lo) {
    hi = __float2bfloat16(v);
    lo = __float2bfloat16(v - __bfloat162float(hi));
}
__device__ __forceinline__ uint32_t packb(__nv_bfloat16 a, __nv_bfloat16 b) {
    __nv_bfloat162 t; t.x = a; t.y = b;
    return *(uint32_t*)&t;
}
__device__ __forceinline__ void mma16816(float* d, const uint32_t* a, uint32_t b0, uint32_t b1) {
    asm("mma.sync.aligned.m16n8k16.row.col.f32.bf16.bf16.f32 "
        "{%0,%1,%2,%3},{%4,%5,%6,%7},{%8,%9},{%0,%1,%2,%3};"
        : "+f"(d[0]), "+f"(d[1]), "+f"(d[2]), "+f"(d[3])
        : "r"(a[0]), "r"(a[1]), "r"(a[2]), "r"(a[3]), "r"(b0), "r"(b1));
}

__global__ __launch_bounds__(THREADS, 2)
void lstm2_tc_kernel(const float* __restrict__ x,
                     const float* __restrict__ W_ih1,
                     const float* __restrict__ W_hh1,
                     const float* __restrict__ b1,
                     const float* __restrict__ W_ih2,
                     const float* __restrict__ W_hh2,
                     const float* __restrict__ b2,
                     const float* __restrict__ W_fc,
                     const float* __restrict__ b_fc,
                     float* __restrict__ out)
{
    extern __shared__ char smem[];
    uint4* __restrict__ BF = (uint4*)(smem + OFF_BF);
    __nv_bfloat16* __restrict__ HShi = (__nv_bfloat16*)(smem + OFF_HSHI);
    __nv_bfloat16* __restrict__ HSlo = (__nv_bfloat16*)(smem + OFF_HSLO);

    const int tid  = threadIdx.x;
    const int w    = tid >> 5;
    const int lane = tid & 31;
    const int gid  = lane >> 2;     // groupID 0..7
    const int tig  = lane & 3;      // thread-in-group 0..3
    const int mt   = w >> 2;        // m-tile 0..1 (16 elements each)
    const int ng   = w & 3;         // n-group 0..3 (5 n-tiles each)

    const float* xp = x + ((long)blockIdx.x * EPB + (tid & 31)) * (T * 3);

    // ---------------- init: zero HS ----------------
    for (int i = tid; i < 32 * PITCH; i += THREADS) {
        HShi[i] = __float2bfloat16(0.0f);
        HSlo[i] = __float2bfloat16(0.0f);
    }
    __syncthreads();
    // x(0) + bias-one columns (cols 80..82 = x, 83 = L1 one, 84 = L2 one)
    if (tid < 32) {
        __nv_bfloat16 h, l;
        #pragma unroll
        for (int c = 0; c < 3; c++) {
            bsplit(__ldg(xp + c), h, l);
            HShi[tid * PITCH + 80 + c] = h;
            HSlo[tid * PITCH + 80 + c] = l;
        }
        HShi[tid * PITCH + 83] = __float2bfloat16(1.0f);
        HShi[tid * PITCH + 84] = __float2bfloat16(1.0f);
    }

    // ---------------- init: pack B fragments ----------------
    // frag f<60: L1 (kt=f/20, nt=f%20); f>=60: L2 (kt=(f-60)/20, nt=(f-60)%20)
    // lane (gid,tig) holds B[k][n]: b0 = k in {kt*16+2tig, +1}, b1 = {kt*16+2tig+8, +9}, n = nt*8+gid
    for (int f = w; f < NFRAG; f += 8) {
        int layer, kt, nt;
        if (f < 60) { layer = 0; kt = f / 20; nt = f % 20; }
        else        { layer = 1; kt = (f - 60) / 20; nt = (f - 60) % 20; }
        int n = nt * 8 + gid;
        int r = (n & 3) * H + (n >> 2);   // PyTorch row = gate*H + unit
        float v[4];
        #pragma unroll
        for (int q = 0; q < 4; q++) {
            int k = kt * 16 + 2 * tig + ((q >> 1) * 8) + (q & 1);
            float val;
            if (layer == 0) {
                if (k < 40)      val = W_hh1[r * H + k];
                else if (k < 43) val = W_ih1[r * 3 + (k - 40)];
                else if (k == 43)val = b1[r];
                else             val = 0.0f;
            } else {
                if (k < 40)      val = W_ih2[r * H + k];
                else if (k < 80) val = W_hh2[r * H + (k - 40)];
                else if (k == 80)val = b2[r];
                else             val = 0.0f;
            }
            v[q] = val;
        }
        __nv_bfloat16 h0, l0, h1, l1, h2, l2, h3, l3;
        bsplit(v[0], h0, l0); bsplit(v[1], h1, l1);
        bsplit(v[2], h2, l2); bsplit(v[3], h3, l3);
        uint4 pk;
        pk.x = packb(h0, h1);   // Bhi reg b0
        pk.y = packb(h2, h3);   // Bhi reg b1
        pk.z = packb(l0, l1);   // Blo reg b0
        pk.w = packb(l2, l3);   // Blo reg b1
        BF[f * 32 + lane] = pk;
    }
    __syncthreads();

    // ---------------- recurrent state ----------------
    float cs1[5][2], cs2[5][2];
    #pragma unroll
    for (int i = 0; i < 5; i++) { cs1[i][0] = cs1[i][1] = 0.0f; cs2[i][0] = cs2[i][1] = 0.0f; }

    const int e0 = mt * 16 + gid;
    const int e1 = e0 + 8;

    // epilogue: D cols (2tig,2tig+1) = gate pair of unit 2nt+(tig>>1); even tig = (i,f), odd = (g,o)
    auto epi = [&](float D[5][4], float cs[5][2], int colbase) {
        #pragma unroll
        for (int ntl = 0; ntl < 5; ntl++) {
            float u0, v0, u1, v1;
            if ((tig & 1) == 0) {
                u0 = sigf(D[ntl][0]); v0 = sigf(D[ntl][1]);     // si, sf (row e0)
                u1 = sigf(D[ntl][2]); v1 = sigf(D[ntl][3]);     // row e1
            } else {
                u0 = tanhfast(D[ntl][0]); v0 = sigf(D[ntl][1]); // tg, so
                u1 = tanhfast(D[ntl][2]); v1 = sigf(D[ntl][3]);
            }
            float g0 = __shfl_xor_sync(0xffffffffu, u0, 1);     // even receives tg
            float g1 = __shfl_xor_sync(0xffffffffu, u1, 1);
            cs[ntl][0] = fmaf(v0, cs[ntl][0], u0 * g0);         // even: c = sf*c + si*tg
            cs[ntl][1] = fmaf(v1, cs[ntl][1], u1 * g1);
            float tc0 = tanhfast(cs[ntl][0]);
            float tc1 = tanhfast(cs[ntl][1]);
            float r0 = __shfl_xor_sync(0xffffffffu, tc0, 1);    // odd receives tanh(c)
            float r1 = __shfl_xor_sync(0xffffffffu, tc1, 1);
            if (tig & 1) {
                int unit = 2 * (ng * 5 + ntl) + (tig >> 1);
                float h0 = v0 * r0;                              // h = so * tanh(c)
                float h1 = v1 * r1;
                __nv_bfloat16 hh, hl;
                bsplit(h0, hh, hl);
                HShi[e0 * PITCH + colbase + unit] = hh;
                HSlo[e0 * PITCH + colbase + unit] = hl;
                bsplit(h1, hh, hl);
                HShi[e1 * PITCH + colbase + unit] = hh;
                HSlo[e1 * PITCH + colbase + unit] = hl;
            }
        }
    };

    float xr0 = 0.f, xr1 = 0.f, xr2 = 0.f;

    for (int t = 0; t < T; t++) {
        // prefetch x(t+1)
        if (tid < 32) {
            int tn = (t + 1 < T) ? (t + 1) : (T - 1);
            xr0 = __ldg(xp + tn * 3 + 0);
            xr1 = __ldg(xp + tn * 3 + 1);
            xr2 = __ldg(xp + tn * 3 + 2);
        }

        // ============ phase 1: L1 MMA (reads h1(t-1), x(t)) ============
        float D[5][4];
        #pragma unroll
        for (int i = 0; i < 5; i++) { D[i][0] = D[i][1] = D[i][2] = D[i][3] = 0.0f; }
        #pragma unroll
        for (int kt = 0; kt < 3; kt++) {
            // A k-col mapping: kt<2 direct; kt2: k 32..39 -> cols 32..39, k 40..47 -> cols 80..87
            int c0 = (kt < 2) ? kt * 16 + 2 * tig : 32 + 2 * tig;
            int c8 = (kt < 2) ? kt * 16 + 2 * tig + 8 : 80 + 2 * tig;
            uint32_t ah[4], al[4];
            ah[0] = *(const uint32_t*)(HShi + e0 * PITCH + c0);
            ah[1] = *(const uint32_t*)(HShi + e1 * PITCH + c0);
            ah[2] = *(const uint32_t*)(HShi + e0 * PITCH + c8);
            ah[3] = *(const uint32_t*)(HShi + e1 * PITCH + c8);
            al[0] = *(const uint32_t*)(HSlo + e0 * PITCH + c0);
            al[1] = *(const uint32_t*)(HSlo + e1 * PITCH + c0);
            al[2] = *(const uint32_t*)(HSlo + e0 * PITCH + c8);
            al[3] = *(const uint32_t*)(HSlo + e1 * PITCH + c8);
            #pragma unroll
            for (int ntl = 0; ntl < 5; ntl++) {
                uint4 bb = BF[(kt * 20 + ng * 5 + ntl) * 32 + lane];
                mma16816(D[ntl], ah, bb.x, bb.y);   // Ahi * Bhi
                mma16816(D[ntl], al, bb.x, bb.y);   // Alo * Bhi
                mma16816(D[ntl], ah, bb.z, bb.w);   // Ahi * Blo
            }
        }
        __syncthreads();

        // ============ phase 2: L1 epilogue -> h1(t); stage x(t+1) ============
        epi(D, cs1, 0);
        if (tid < 32) {
            __nv_bfloat16 h, l;
            bsplit(xr0, h, l); HShi[tid * PITCH + 80] = h; HSlo[tid * PITCH + 80] = l;
            bsplit(xr1, h, l); HShi[tid * PITCH + 81] = h; HSlo[tid * PITCH + 81] = l;
            bsplit(xr2, h, l); HShi[tid * PITCH + 82] = h; HSlo[tid * PITCH + 82] = l;
        }
        __syncthreads();

        // ============ phase 3: L2 MMA (reads h1(t), h2(t-1)) ============
        #pragma unroll
        for (int i = 0; i < 5; i++) { D[i][0] = D[i][1] = D[i][2] = D[i][3] = 0.0f; }
        #pragma unroll
        for (int kt = 0; kt < 6; kt++) {
            // kt<5 direct (cols 0..79); kt5: k=80 (bias) -> col 84 (=1.0), k 81..95 -> cols 85..99 (B rows zero)
            int c0 = (kt < 5) ? kt * 16 + 2 * tig : 84 + 2 * tig;
            int c8 = (kt < 5) ? kt * 16 + 2 * tig + 8 : 92 + 2 * tig;
            uint32_t ah[4], al[4];
            ah[0] = *(const uint32_t*)(HShi + e0 * PITCH + c0);
            ah[1] = *(const uint32_t*)(HShi + e1 * PITCH + c0);
            ah[2] = *(const uint32_t*)(HShi + e0 * PITCH + c8);
            ah[3] = *(const uint32_t*)(HShi + e1 * PITCH + c8);
            al[0] = *(const uint32_t*)(HSlo + e0 * PITCH + c0);
            al[1] = *(const uint32_t*)(HSlo + e1 * PITCH + c0);
            al[2] = *(const uint32_t*)(HSlo + e0 * PITCH + c8);
            al[3] = *(const uint32_t*)(HSlo + e1 * PITCH + c8);
            #pragma unroll
            for (int ntl = 0; ntl < 5; ntl++) {
                uint4 bb = BF[(60 + kt * 20 + ng * 5 + ntl) * 32 + lane];
                mma16816(D[ntl], ah, bb.x, bb.y);
                mma16816(D[ntl], al, bb.x, bb.y);
                mma16816(D[ntl], ah, bb.z, bb.w);
            }
        }
        __syncthreads();

        // ============ phase 4: L2 epilogue -> h2(t) ============
        epi(D, cs2, 40);
        // no barrier here: next phase-1 doesn't touch h2; phase-3(t+1) is
        // separated from these writes by the phase-1 and phase-2 barriers.
    }
    __syncthreads();

    // ---------------- FC epilogue ----------------
    if (tid < 64) {
        int e = tid >> 1, q = tid & 1;
        float acc = __ldg(b_fc + q);
        #pragma unroll 8
        for (int u = 0; u < H; u++) {
            float h = __bfloat162float(HShi[e * PITCH + 40 + u])
                    + __bfloat162float(HSlo[e * PITCH + 40 + u]);
            acc = fmaf(h, __ldg(W_fc + q * H + u), acc);
        }
        out[((long)blockIdx.x * EPB + e) * 2 + q] = acc;
    }
}

extern "C" void kernel_launch(void* const* d_in, const int* in_sizes, int n_in,
                              void* d_out, int out_size)
{
    const float* x     = (const float*)d_in[0];
    const float* W_ih1 = (const float*)d_in[1];
    const float* W_hh1 = (const float*)d_in[2];
    const float* b1    = (const float*)d_in[3];
    const float* W_ih2 = (const float*)d_in[4];
    const float* W_hh2 = (const float*)d_in[5];
    const float* b2    = (const float*)d_in[6];
    const float* W_fc  = (const float*)d_in[7];
    const float* b_fc  = (const float*)d_in[8];
    float* out = (float*)d_out;

    cudaFuncSetAttribute(lstm2_tc_kernel,
                         cudaFuncAttributeMaxDynamicSharedMemorySize, SMEM_BYTES);

    lstm2_tc_kernel<<<NBLOCKS, THREADS, SMEM_BYTES>>>(
        x, W_ih1, W_hh1, b1, W_ih2, W_hh2, b2, W_fc, b_fc, out);
}